// round 14
// baseline (speedup 1.0000x reference)
#include <cuda_runtime.h>
#include <cstdint>

#define NN   4096
#define IND  256
#define HID1 64
#define NH1  4
#define F1T  256
#define F2T  128

typedef unsigned long long u64;

__device__ float g_Wh1[NN * F1T];          // tf32-rounded
__device__ float g_h1 [NN * F1T];
__device__ float g_Wh2[NN * F2T];          // tf32-rounded
__device__ float g_e1p_h[NH1 * NN], g_e1n_h[NH1 * NN];
__device__ float g_e2p_h[NH1 * NN], g_e2n_h[NH1 * NN];
__device__ float g_e1p_o[NN], g_e1n_o[NN], g_e2p_o[NN], g_e2n_o[NN];
__device__ unsigned g_adjbits[NN * (NN / 32)];

__device__ __forceinline__ u64 pack2(float lo, float hi) {
    return (u64)__float_as_uint(lo) | ((u64)__float_as_uint(hi) << 32);
}
__device__ __forceinline__ float lo2(u64 v) { return __uint_as_float((unsigned)v); }
__device__ __forceinline__ float hi2(u64 v) { return __uint_as_float((unsigned)(v >> 32)); }
__device__ __forceinline__ u64 fma2(u64 a, u64 b, u64 c) {
    u64 d;
    asm("fma.rn.f32x2 %0, %1, %2, %3;" : "=l"(d) : "l"(a), "l"(b), "l"(c));
    return d;
}
__device__ __forceinline__ unsigned cvt_tf32(float x) {
    unsigned u;
    asm("cvt.rna.tf32.f32 %0, %1;" : "=r"(u) : "f"(x));
    return u;
}
__device__ __forceinline__ void mma_tf32(float d[4],
        unsigned a0, unsigned a1, unsigned a2, unsigned a3,
        unsigned b0, unsigned b1) {
    asm volatile(
        "mma.sync.aligned.m16n8k8.row.col.f32.tf32.tf32.f32 "
        "{%0,%1,%2,%3}, {%4,%5,%6,%7}, {%8,%9}, {%0,%1,%2,%3};"
        : "+f"(d[0]), "+f"(d[1]), "+f"(d[2]), "+f"(d[3])
        : "r"(a0), "r"(a1), "r"(a2), "r"(a3), "r"(b0), "r"(b1));
}
__device__ __forceinline__ unsigned sptr(const void* p) {
    return (unsigned)__cvta_generic_to_shared(p);
}
__device__ __forceinline__ void cp16(unsigned dst, const void* src) {
    asm volatile("cp.async.ca.shared.global [%0], [%1], 16;" :: "r"(dst), "l"(src) : "memory");
}
__device__ __forceinline__ void cp4(unsigned dst, const void* src) {
    asm volatile("cp.async.ca.shared.global [%0], [%1], 4;" :: "r"(dst), "l"(src) : "memory");
}
__device__ __forceinline__ void cp_commit() {
    asm volatile("cp.async.commit_group;" ::: "memory");
}
template <int N>
__device__ __forceinline__ void cp_wait() {
    asm volatile("cp.async.wait_group %0;" :: "n"(N) : "memory");
}

// ---------------- adj bit-pack ----------------
__global__ void adjbits_k(const int* __restrict__ adj) {
    const int row = blockIdx.x, w = threadIdx.x >> 5, lane = threadIdx.x & 31;
#pragma unroll 4
    for (int k = 0; k < 32; k++) {
        int col = w * 1024 + k * 32 + lane;
        unsigned m = __ballot_sync(0xffffffffu, adj[row * NN + col] > 0);
        if (lane == 0) g_adjbits[row * (NN / 32) + w * 32 + k] = m;
    }
}

// ---------------- GEMM (SIMT, proven), tf32-rounded output ----------------
template <int FCOLS, bool HEADS_B>
__device__ __forceinline__ void gemm_body(const float* __restrict__ A, const float* __restrict__ B,
                                          float* __restrict__ C) {
    constexpr int K = 256, XPAD = 36, FPT = FCOLS / 64;
    constexpr int NCB = 32 * FCOLS / 2048;
    const int tid = threadIdx.x;
    const int feat0 = (tid & 63) * FPT;
    const int r0 = (tid >> 6) * 4;
    const int row0 = blockIdx.x * 32;
    __shared__ __align__(16) float x_s[2][32 * XPAD];
    __shared__ __align__(16) float b_s[2][32 * FCOLS];
    auto issue_tile = [&](int buf, int k0) {
#pragma unroll
        for (int i = 0; i < 2; i++) {
            int e = i * 512 + tid;
            int r = e & 31, kk = e >> 5;
            cp4(sptr(&x_s[buf][kk * XPAD + r]), &A[(row0 + r) * K + k0 + kk]);
        }
#pragma unroll
        for (int c = 0; c < NCB; c++) {
            int flat = c * 2048 + tid * 4;
            int kk = flat / FCOLS, feat = flat % FCOLS;
            const float* src = HEADS_B
                ? &B[(feat >> 6) * (IND * HID1) + (kk + k0) * HID1 + (feat & 63)]
                : &B[(kk + k0) * FCOLS + feat];
            cp16(sptr(&b_s[buf][flat]), src);
        }
        cp_commit();
    };
    u64 acc[FPT][2];
#pragma unroll
    for (int f = 0; f < FPT; f++) { acc[f][0] = 0ull; acc[f][1] = 0ull; }
    issue_tile(0, 0);
    for (int t = 0; t < K / 32; t++) {
        if (t + 1 < K / 32) { issue_tile((t + 1) & 1, (t + 1) * 32); cp_wait<1>(); }
        else                { cp_wait<0>(); }
        __syncthreads();
        const float* xs = x_s[t & 1];
        const float* bs = b_s[t & 1];
#pragma unroll 8
        for (int kk = 0; kk < 32; kk++) {
            ulonglong2 pv = *(const ulonglong2*)&xs[kk * XPAD + r0];
            float wv[FPT];
            if constexpr (FPT == 4) {
                float4 v = *(const float4*)&bs[kk * FCOLS + feat0];
                wv[0] = v.x; wv[1] = v.y; wv[2] = v.z; wv[3] = v.w;
            } else {
                float2 v = *(const float2*)&bs[kk * FCOLS + feat0];
                wv[0] = v.x; wv[1] = v.y;
            }
#pragma unroll
            for (int f = 0; f < FPT; f++) {
                u64 w2 = pack2(wv[f], wv[f]);
                acc[f][0] = fma2(pv.x, w2, acc[f][0]);
                acc[f][1] = fma2(pv.y, w2, acc[f][1]);
            }
        }
        __syncthreads();
    }
#pragma unroll
    for (int i = 0; i < 4; i++) {
        float v[FPT];
#pragma unroll
        for (int f = 0; f < FPT; f++) {
            float raw = (i & 1) ? hi2(acc[f][i >> 1]) : lo2(acc[f][i >> 1]);
            v[f] = __uint_as_float(cvt_tf32(raw));
        }
        float* cp = &C[(row0 + r0 + i) * FCOLS + feat0];
        if constexpr (FPT == 4) *(float4*)cp = make_float4(v[0], v[1], v[2], v[3]);
        else                    *(float2*)cp = make_float2(v[0], v[1]);
    }
}
__global__ void __launch_bounds__(512, 1) gemm1_k(const float* __restrict__ x, const float* __restrict__ W) {
    gemm_body<F1T, true>(x, W, g_Wh1);
}
__global__ void __launch_bounds__(512, 1) gemm2_k(const float* __restrict__ W) {
    gemm_body<F2T, false>(g_h1, W, g_Wh2);
}

// ---------------- f-vectors (factored exp) ----------------
__global__ void fvec1_k(const float* __restrict__ a_heads) {
    const int i = blockIdx.x, t = threadIdx.x, lane = t & 31, w = t >> 5;
    float p1[NH1], p2[NH1];
#pragma unroll
    for (int h = 0; h < NH1; h++) {
        float v = g_Wh1[i * F1T + h * HID1 + t];
        p1[h] = v * a_heads[h * (2 * HID1) + t];
        p2[h] = v * a_heads[h * (2 * HID1) + HID1 + t];
    }
#pragma unroll
    for (int off = 16; off; off >>= 1)
#pragma unroll
        for (int h = 0; h < NH1; h++) {
            p1[h] += __shfl_down_sync(0xffffffffu, p1[h], off);
            p2[h] += __shfl_down_sync(0xffffffffu, p2[h], off);
        }
    __shared__ float red[2][2 * NH1];
    if (lane == 0)
#pragma unroll
        for (int h = 0; h < NH1; h++) { red[w][h] = p1[h]; red[w][NH1 + h] = p2[h]; }
    __syncthreads();
    if (t == 0)
#pragma unroll
        for (int h = 0; h < NH1; h++) {
            float f1 = red[0][h] + red[1][h];
            float f2 = red[0][NH1 + h] + red[1][NH1 + h];
            g_e1p_h[h * NN + i] = __expf(f1);
            g_e1n_h[h * NN + i] = __expf(0.5f * f1);
            g_e2p_h[h * NN + i] = __expf(f2);
            g_e2n_h[h * NN + i] = __expf(0.5f * f2);
        }
}
__global__ void fvec2_k(const float* __restrict__ a_out) {
    const int i = blockIdx.x, t = threadIdx.x, lane = t & 31, w = t >> 5;
    float v = g_Wh2[i * F2T + t];
    float p1 = v * a_out[t], p2 = v * a_out[F2T + t];
#pragma unroll
    for (int off = 16; off; off >>= 1) {
        p1 += __shfl_down_sync(0xffffffffu, p1, off);
        p2 += __shfl_down_sync(0xffffffffu, p2, off);
    }
    __shared__ float red[4][2];
    if (lane == 0) { red[w][0] = p1; red[w][1] = p2; }
    __syncthreads();
    if (t == 0) {
        float f1 = red[0][0] + red[1][0] + red[2][0] + red[3][0];
        float f2 = red[0][1] + red[1][1] + red[2][1] + red[3][1];
        g_e1p_o[i] = __expf(f1);
        g_e1n_o[i] = __expf(0.5f * f1);
        g_e2p_o[i] = __expf(f2);
        g_e2n_o[i] = __expf(0.5f * f2);
    }
}

// =======================================================================
// mma.sync tf32 attention, 32-row blocks, direct-global B operands.
// block = 32 rows x F feats, 512 threads (16 warps), grid 128.
// warp: rowgroup rg = warp>>3 (16 rows), feats = (warp&7)*F/8 (CHUNKS n8).
// Per 32-j tile: sync -> STS p(t) regs -> sync ->
//   [ LDG B(t+1) frags -> regs | mma(t): LDS A frags + HMMA ].
// No smem staging of Wh at all. Denominator = fp32 sum of tf32-rounded p.
// =======================================================================
template <int F, int NH>
__device__ __forceinline__ void attn_body(const float* __restrict__ Wh,
                                          const float* __restrict__ e1p,
                                          const float* __restrict__ e1n,
                                          const float* __restrict__ e2p,
                                          const float* __restrict__ e2n,
                                          float* __restrict__ out) {
    constexpr int TJ = 32, NT = NN / TJ;         // 128 tiles
    constexpr int FW = F / 8;                    // feats per warp: 32 / 16
    constexpr int CHUNKS = FW / 8;               // 4 / 2
    const int tid  = threadIdx.x;
    const int lane = tid & 31, warp = tid >> 5;
    const int g = lane >> 2, c = lane & 3;
    const int rg = warp >> 3;                    // rowgroup 0/1
    const int feat0 = (warp & 7) * FW;
    const int hw = feat0 / (F / NH);             // head of this mma warp
    const int row0 = blockIdx.x * 32;

    __shared__ __align__(16) float p_s[2][NH * 16 * 36];   // [rg][h][r][36]
    __shared__ float denom_s[2][16 * NH];

    float d[CHUNKS][4];
#pragma unroll
    for (int q = 0; q < CHUNKS; q++)
#pragma unroll
        for (int i = 0; i < 4; i++) d[q][i] = 0.0f;

    // ---- p-compute role ----
    // NH==4: ph = tid>>7 (head), lt = tid&127: pr = lt>>3 (16 rows),
    //        pcq = (lt&7)*4. Thread covers BOTH rowgroups for (ph, pr).
    // NH==1: pr = tid>>4 (32 rows), pj2 = (tid&15)*2 (2 j cols).
    int ph, pr, pcq;
    if constexpr (NH == 4) { ph = tid >> 7; pr = (tid >> 3) & 15; pcq = (tid & 7) << 2; }
    else                   { ph = 0;        pr = tid >> 4;        pcq = (tid & 15) << 1; }
    float E1pv[2], E1nv[2], dsum[2];
    if constexpr (NH == 4) {
        E1pv[0] = e1p[ph * NN + row0 + pr];       E1nv[0] = e1n[ph * NN + row0 + pr];
        E1pv[1] = e1p[ph * NN + row0 + 16 + pr];  E1nv[1] = e1n[ph * NN + row0 + 16 + pr];
    } else {
        E1pv[0] = e1p[row0 + pr];                 E1nv[0] = e1n[row0 + pr];
        E1pv[1] = 0.f; E1nv[1] = 0.f;
    }
    dsum[0] = 0.0f; dsum[1] = 0.0f;

    auto store_p = [&](int t) {
        const int j0 = t * TJ;
        if constexpr (NH == 4) {
            float4 q2p = *(const float4*)&e2p[ph * NN + j0 + pcq];
            float4 q2n = *(const float4*)&e2n[ph * NN + j0 + pcq];
            float ap[4] = {q2p.x, q2p.y, q2p.z, q2p.w};
            float an[4] = {q2n.x, q2n.y, q2n.z, q2n.w};
#pragma unroll
            for (int m = 0; m < 2; m++) {
                unsigned bw = g_adjbits[(row0 + m * 16 + pr) * (NN / 32) + t];
                float pv[4];
#pragma unroll
                for (int i = 0; i < 4; i++) {
                    float pm = fmaxf(E1pv[m] * ap[i], E1nv[m] * an[i]);
                    float p  = ((bw >> (pcq + i)) & 1u) ? pm : 0.0f;
                    pv[i] = __uint_as_float(cvt_tf32(p));
                    dsum[m] += pv[i];
                }
                *(float4*)&p_s[m][(ph * 16 + pr) * 36 + pcq] =
                    make_float4(pv[0], pv[1], pv[2], pv[3]);
            }
        } else {
            float2 q2p = *(const float2*)&e2p[j0 + pcq];
            float2 q2n = *(const float2*)&e2n[j0 + pcq];
            unsigned bw = g_adjbits[(row0 + pr) * (NN / 32) + t];
            float p0 = fmaxf(E1pv[0] * q2p.x, E1nv[0] * q2n.x);
            float p1 = fmaxf(E1pv[0] * q2p.y, E1nv[0] * q2n.y);
            p0 = ((bw >> pcq) & 1u) ? p0 : 0.0f;
            p1 = ((bw >> (pcq + 1)) & 1u) ? p1 : 0.0f;
            p0 = __uint_as_float(cvt_tf32(p0));
            p1 = __uint_as_float(cvt_tf32(p1));
            dsum[0] += p0 + p1;
            *(float2*)&p_s[pr >> 4][(pr & 15) * 36 + pcq] = make_float2(p0, p1);
        }
    };

    auto load_B = [&](int t, float (&Bd)[CHUNKS][4][2]) {
        const int j0 = t * TJ;
#pragma unroll
        for (int ks = 0; ks < 4; ks++) {
            const float* base0 = &Wh[(j0 + 8 * ks + c) * F + feat0 + g];
            const float* base1 = &Wh[(j0 + 8 * ks + c + 4) * F + feat0 + g];
#pragma unroll
            for (int q = 0; q < CHUNKS; q++) {
                Bd[q][ks][0] = base0[q * 8];
                Bd[q][ks][1] = base1[q * 8];
            }
        }
    };

    auto do_mma = [&](float (&Bc)[CHUNKS][4][2]) {
        const float* pa = &p_s[rg][hw * 16 * 36];
#pragma unroll
        for (int ks = 0; ks < 4; ks++) {
            unsigned a0 = __float_as_uint(pa[g * 36 + 8 * ks + c]);
            unsigned a1 = __float_as_uint(pa[(g + 8) * 36 + 8 * ks + c]);
            unsigned a2 = __float_as_uint(pa[g * 36 + 8 * ks + c + 4]);
            unsigned a3 = __float_as_uint(pa[(g + 8) * 36 + 8 * ks + c + 4]);
#pragma unroll
            for (int q = 0; q < CHUNKS; q++)
                mma_tf32(d[q], a0, a1, a2, a3,
                         __float_as_uint(Bc[q][ks][0]), __float_as_uint(Bc[q][ks][1]));
        }
    };

    float B2a[CHUNKS][4][2], B2b[CHUNKS][4][2];
    load_B(0, B2a);

    auto step = [&](int t, float (&Bc)[CHUNKS][4][2], float (&Bn)[CHUNKS][4][2]) {
        __syncthreads();               // mma(t-1) done reading p_s
        store_p(t);
        __syncthreads();               // p(t) visible
        if (t + 1 < NT) load_B(t + 1, Bn);
        do_mma(Bc);
    };

    for (int t = 0; t < NT; t += 2) {
        step(t,     B2a, B2b);
        step(t + 1, B2b, B2a);
    }

    // ---- denominator reduce + publish ----
    __syncthreads();
    if constexpr (NH == 4) {
#pragma unroll
        for (int m = 0; m < 2; m++) {
            float v = dsum[m];
            v += __shfl_xor_sync(0xffffffffu, v, 1);
            v += __shfl_xor_sync(0xffffffffu, v, 2);
            v += __shfl_xor_sync(0xffffffffu, v, 4);
            if ((lane & 7) == 0) denom_s[m][pr * NH1 + ph] = v;
        }
    } else {
        float v = dsum[0];
        v += __shfl_xor_sync(0xffffffffu, v, 1);
        v += __shfl_xor_sync(0xffffffffu, v, 2);
        v += __shfl_xor_sync(0xffffffffu, v, 4);
        v += __shfl_xor_sync(0xffffffffu, v, 8);
        if ((lane & 15) == 0) denom_s[pr >> 4][pr & 15] = v;
    }
    __syncthreads();

    // ---- normalize + ELU + store ----
    const float inv1 = 1.0f / denom_s[rg][g * NH + hw];
    const float inv2 = 1.0f / denom_s[rg][(g + 8) * NH + hw];
    const int orow = row0 + rg * 16;
#pragma unroll
    for (int q = 0; q < CHUNKS; q++) {
        int feat = feat0 + q * 8 + 2 * c;
        float v0 = d[q][0] * inv1, v1 = d[q][1] * inv1;
        float v2 = d[q][2] * inv2, v3 = d[q][3] * inv2;
        v0 = v0 > 0.0f ? v0 : expm1f(v0);
        v1 = v1 > 0.0f ? v1 : expm1f(v1);
        v2 = v2 > 0.0f ? v2 : expm1f(v2);
        v3 = v3 > 0.0f ? v3 : expm1f(v3);
        *(float2*)&out[(orow + g) * F + feat]     = make_float2(v0, v1);
        *(float2*)&out[(orow + g + 8) * F + feat] = make_float2(v2, v3);
    }
}

__global__ void __launch_bounds__(512, 1) attn1_k() {
    attn_body<F1T, NH1>(g_Wh1, g_e1p_h, g_e1n_h, g_e2p_h, g_e2n_h, g_h1);
}
__global__ void __launch_bounds__(512, 1) attn2_k(float* __restrict__ out) {
    attn_body<F2T, 1>(g_Wh2, g_e1p_o, g_e1n_o, g_e2p_o, g_e2n_o, out);
}

// ---------------- launch ----------------
extern "C" void kernel_launch(void* const* d_in, const int* in_sizes, int n_in,
                              void* d_out, int out_size) {
    const float* x       = (const float*)d_in[0];
    const int*   adj     = (const int*)  d_in[1];
    const float* W_heads = (const float*)d_in[2];
    const float* a_heads = (const float*)d_in[3];
    const float* W_out   = (const float*)d_in[4];
    const float* a_out   = (const float*)d_in[5];
    float* out = (float*)d_out;

    adjbits_k<<<NN, 128>>>(adj);
    gemm1_k<<<NN / 32, 512>>>(x, W_heads);
    fvec1_k<<<NN, 64>>>(a_heads);
    attn1_k<<<NN / 32, 512>>>();
    gemm2_k<<<NN / 32, 512>>>(W_out);
    fvec2_k<<<NN, 128>>>(a_out);
    attn2_k<<<NN / 32, 512>>>(out);
}

// round 15
// speedup vs baseline: 1.8913x; 1.8913x over previous
#include <cuda_runtime.h>

#define NN   4096
#define IND  256
#define HID1 64
#define NH1  4
#define F1T  256
#define F2T  128

typedef unsigned long long u64;

// ---- scratch (device globals; no allocation allowed) ----
__device__ float g_Wh1[NN * F1T];          // tf32-rounded
__device__ float g_h1 [NN * F1T];          // layer-1 output (fp32)
__device__ float g_Wh2[NN * F2T];          // tf32-rounded
__device__ float g_e1p_h[NH1 * NN], g_e1n_h[NH1 * NN];
__device__ float g_e2p_h[NH1 * NN], g_e2n_h[NH1 * NN];
__device__ float g_e1p_o[NN], g_e1n_o[NN], g_e2p_o[NN], g_e2n_o[NN];
__device__ unsigned g_adjbits[NN * (NN / 32)];   // 2MB packed mask

// ---- packed fp32x2 helpers (sm_103a) ----
__device__ __forceinline__ u64 pack2(float lo, float hi) {
    return (u64)__float_as_uint(lo) | ((u64)__float_as_uint(hi) << 32);
}
__device__ __forceinline__ float lo2(u64 v) { return __uint_as_float((unsigned)v); }
__device__ __forceinline__ float hi2(u64 v) { return __uint_as_float((unsigned)(v >> 32)); }
__device__ __forceinline__ u64 fma2(u64 a, u64 b, u64 c) {
    u64 d;
    asm("fma.rn.f32x2 %0, %1, %2, %3;" : "=l"(d) : "l"(a), "l"(b), "l"(c));
    return d;
}

// ---- tf32 / mma helpers ----
__device__ __forceinline__ unsigned cvt_tf32(float x) {
    unsigned u;
    asm("cvt.rna.tf32.f32 %0, %1;" : "=r"(u) : "f"(x));
    return u;
}
__device__ __forceinline__ void mma_tf32(float d[4],
        unsigned a0, unsigned a1, unsigned a2, unsigned a3,
        unsigned b0, unsigned b1) {
    asm volatile(
        "mma.sync.aligned.m16n8k8.row.col.f32.tf32.tf32.f32 "
        "{%0,%1,%2,%3}, {%4,%5,%6,%7}, {%8,%9}, {%0,%1,%2,%3};"
        : "+f"(d[0]), "+f"(d[1]), "+f"(d[2]), "+f"(d[3])
        : "r"(a0), "r"(a1), "r"(a2), "r"(a3), "r"(b0), "r"(b1));
}

// ---- cp.async helpers ----
__device__ __forceinline__ unsigned sptr(const void* p) {
    return (unsigned)__cvta_generic_to_shared(p);
}
__device__ __forceinline__ void cp16(unsigned dst, const void* src) {
    asm volatile("cp.async.ca.shared.global [%0], [%1], 16;" :: "r"(dst), "l"(src) : "memory");
}
__device__ __forceinline__ void cp4(unsigned dst, const void* src) {
    asm volatile("cp.async.ca.shared.global [%0], [%1], 4;" :: "r"(dst), "l"(src) : "memory");
}
__device__ __forceinline__ void cp_commit() {
    asm volatile("cp.async.commit_group;" ::: "memory");
}
template <int N>
__device__ __forceinline__ void cp_wait() {
    asm volatile("cp.async.wait_group %0;" :: "n"(N) : "memory");
}

// =======================================================================
// adj bit-pack: g_adjbits[row][w] bit l = adj[row][32w+l] > 0
// =======================================================================
__global__ void adjbits_k(const int* __restrict__ adj) {
    const int row  = blockIdx.x;
    const int w    = threadIdx.x >> 5;
    const int lane = threadIdx.x & 31;
#pragma unroll 4
    for (int k = 0; k < 32; k++) {
        int col = w * 1024 + k * 32 + lane;
        unsigned m = __ballot_sync(0xffffffffu, adj[row * NN + col] > 0);
        if (lane == 0) g_adjbits[row * (NN / 32) + w * 32 + k] = m;
    }
}

// =======================================================================
// GEMM: C = A[4096,256] @ B, output tf32-rounded (proven)
// =======================================================================
template <int FCOLS, bool HEADS_B>
__device__ __forceinline__ void gemm_body(const float* __restrict__ A,
                                          const float* __restrict__ B,
                                          float* __restrict__ C) {
    constexpr int K = 256, XPAD = 36, FPT = FCOLS / 64;
    constexpr int NCB = 32 * FCOLS / 2048;
    const int tid   = threadIdx.x;
    const int feat0 = (tid & 63) * FPT;
    const int r0    = (tid >> 6) * 4;
    const int row0  = blockIdx.x * 32;

    __shared__ __align__(16) float x_s[2][32 * XPAD];
    __shared__ __align__(16) float b_s[2][32 * FCOLS];

    auto issue_tile = [&](int buf, int k0) {
#pragma unroll
        for (int i = 0; i < 2; i++) {
            int e = i * 512 + tid;
            int r = e & 31, kk = e >> 5;
            cp4(sptr(&x_s[buf][kk * XPAD + r]), &A[(row0 + r) * K + k0 + kk]);
        }
#pragma unroll
        for (int c = 0; c < NCB; c++) {
            int flat = c * 2048 + tid * 4;
            int kk = flat / FCOLS, feat = flat % FCOLS;
            const float* src = HEADS_B
                ? &B[(feat >> 6) * (IND * HID1) + (k0 + kk) * HID1 + (feat & 63)]
                : &B[(k0 + kk) * FCOLS + feat];
            cp16(sptr(&b_s[buf][flat]), src);
        }
        cp_commit();
    };

    u64 acc[FPT][2];
#pragma unroll
    for (int f = 0; f < FPT; f++) { acc[f][0] = 0ull; acc[f][1] = 0ull; }

    issue_tile(0, 0);
    for (int t = 0; t < K / 32; t++) {
        if (t + 1 < K / 32) { issue_tile((t + 1) & 1, (t + 1) * 32); cp_wait<1>(); }
        else                { cp_wait<0>(); }
        __syncthreads();
        const float* xs = x_s[t & 1];
        const float* bs = b_s[t & 1];
#pragma unroll 8
        for (int kk = 0; kk < 32; kk++) {
            ulonglong2 pv = *(const ulonglong2*)&xs[kk * XPAD + r0];
            float wv[FPT];
            if constexpr (FPT == 4) {
                float4 v = *(const float4*)&bs[kk * FCOLS + feat0];
                wv[0] = v.x; wv[1] = v.y; wv[2] = v.z; wv[3] = v.w;
            } else {
                float2 v = *(const float2*)&bs[kk * FCOLS + feat0];
                wv[0] = v.x; wv[1] = v.y;
            }
#pragma unroll
            for (int f = 0; f < FPT; f++) {
                u64 w2 = pack2(wv[f], wv[f]);
                acc[f][0] = fma2(pv.x, w2, acc[f][0]);
                acc[f][1] = fma2(pv.y, w2, acc[f][1]);
            }
        }
        __syncthreads();
    }
#pragma unroll
    for (int i = 0; i < 4; i++) {
        float v[FPT];
#pragma unroll
        for (int f = 0; f < FPT; f++) {
            float raw = (i & 1) ? hi2(acc[f][i >> 1]) : lo2(acc[f][i >> 1]);
            v[f] = __uint_as_float(cvt_tf32(raw));
        }
        float* cp = &C[(row0 + r0 + i) * FCOLS + feat0];
        if constexpr (FPT == 4) *(float4*)cp = make_float4(v[0], v[1], v[2], v[3]);
        else                    *(float2*)cp = make_float2(v[0], v[1]);
    }
}

__global__ void __launch_bounds__(512, 1) gemm1_k(const float* __restrict__ x,
                                                  const float* __restrict__ W_heads) {
    gemm_body<F1T, true>(x, W_heads, g_Wh1);
}
__global__ void __launch_bounds__(512, 1) gemm2_k(const float* __restrict__ W_out) {
    gemm_body<F2T, false>(g_h1, W_out, g_Wh2);
}

// =======================================================================
// f-vector kernels: f = Wh . a halves, store factored-exp forms
// =======================================================================
__global__ void fvec1_k(const float* __restrict__ a_heads) {
    const int i = blockIdx.x;
    const int t = threadIdx.x;            // 0..63
    const int lane = t & 31, w = t >> 5;
    float p1[NH1], p2[NH1];
#pragma unroll
    for (int h = 0; h < NH1; h++) {
        float v = g_Wh1[i * F1T + h * HID1 + t];
        p1[h] = v * a_heads[h * (2 * HID1) + t];
        p2[h] = v * a_heads[h * (2 * HID1) + HID1 + t];
    }
#pragma unroll
    for (int off = 16; off; off >>= 1)
#pragma unroll
        for (int h = 0; h < NH1; h++) {
            p1[h] += __shfl_down_sync(0xffffffffu, p1[h], off);
            p2[h] += __shfl_down_sync(0xffffffffu, p2[h], off);
        }
    __shared__ float red[2][2 * NH1];
    if (lane == 0) {
#pragma unroll
        for (int h = 0; h < NH1; h++) { red[w][h] = p1[h]; red[w][NH1 + h] = p2[h]; }
    }
    __syncthreads();
    if (t == 0) {
#pragma unroll
        for (int h = 0; h < NH1; h++) {
            float f1 = red[0][h] + red[1][h];
            float f2 = red[0][NH1 + h] + red[1][NH1 + h];
            g_e1p_h[h * NN + i] = __expf(f1);
            g_e1n_h[h * NN + i] = __expf(0.5f * f1);
            g_e2p_h[h * NN + i] = __expf(f2);
            g_e2n_h[h * NN + i] = __expf(0.5f * f2);
        }
    }
}

__global__ void fvec2_k(const float* __restrict__ a_out) {
    const int i = blockIdx.x;
    const int t = threadIdx.x;            // 0..127
    const int lane = t & 31, w = t >> 5;
    float v  = g_Wh2[i * F2T + t];
    float p1 = v * a_out[t];
    float p2 = v * a_out[F2T + t];
#pragma unroll
    for (int off = 16; off; off >>= 1) {
        p1 += __shfl_down_sync(0xffffffffu, p1, off);
        p2 += __shfl_down_sync(0xffffffffu, p2, off);
    }
    __shared__ float red[4][2];
    if (lane == 0) { red[w][0] = p1; red[w][1] = p2; }
    __syncthreads();
    if (t == 0) {
        float f1 = red[0][0] + red[1][0] + red[2][0] + red[3][0];
        float f2 = red[0][1] + red[1][1] + red[2][1] + red[3][1];
        g_e1p_o[i] = __expf(f1);
        g_e1n_o[i] = __expf(0.5f * f1);
        g_e2p_o[i] = __expf(f2);
        g_e2n_o[i] = __expf(0.5f * f2);
    }
}

// =======================================================================
// Tensor-core attention (tf32 mma.sync, flash), 2 blocks/SM occupancy:
// SINGLE-buffered Wh stage (smem 43KB) so two blocks co-reside; each
// block's cp-wait/barrier stalls are covered by the other block.
// block = 16 rows x F feats, 512 threads, grid 256 (one wave at occ 2).
// Per tile: sync -> STS p(t) -> issue wh(t) -> compute p(t+1) regs
//           (overlaps cp latency) -> wait+sync -> mma(t).
// denominator = fp32 sum of the SAME tf32-rounded p values.
// =======================================================================
template <int F, int NH>
__device__ __forceinline__ void attn_body(const float* __restrict__ Wh,
                                          const float* __restrict__ e1p,
                                          const float* __restrict__ e1n,
                                          const float* __restrict__ e2p,
                                          const float* __restrict__ e2n,
                                          float* __restrict__ out) {
    constexpr int TJ = 32, NT = NN / TJ;
    constexpr int WS = F + 8;                    // 264 / 136 : == 8 mod 32
    constexpr int CHUNKS = F / 128;              // n8 chunks per warp (2 / 1)
    constexpr int NCW = (TJ * F / 4) / 512;      // cp16 per thread per tile
    constexpr int PV = (NH == 4) ? 4 : 1;
    const int tid  = threadIdx.x;
    const int lane = tid & 31, warp = tid >> 5;
    const int g = lane >> 2, c = lane & 3;
    const int row0 = blockIdx.x * 16;
    const int hw   = (warp * NH) >> 4;

    __shared__ __align__(16) float p_s[NH * 16 * 36];   // single buffer
    __shared__ __align__(16) float wh_s[TJ * WS];       // SINGLE buffer
    __shared__ float denom_s[NH * 16];

    auto issue_wh = [&](int j0) {
#pragma unroll
        for (int cc = 0; cc < NCW; cc++) {
            int fc = cc * 512 + tid;
            int k = fc / (F / 4), off = (fc % (F / 4)) * 4;
            cp16(sptr(&wh_s[k * WS + off]), &Wh[(j0 + k) * F + off]);
        }
        cp_commit();
    };

    float d[CHUNKS][4];
#pragma unroll
    for (int q = 0; q < CHUNKS; q++)
#pragma unroll
        for (int i = 0; i < 4; i++) d[q][i] = 0.0f;

    // p-compute role
    int ph, pr, pcq;
    if constexpr (NH == 4) { ph = tid >> 7; pr = (tid >> 3) & 15; pcq = (tid & 7) << 2; }
    else                   { ph = 0;        pr = tid >> 5;        pcq = tid & 31; }
    const float E1pv = e1p[ph * NN + row0 + pr];
    const float E1nv = e1n[ph * NN + row0 + pr];
    float dsum = 0.0f;

    float4 c2p4, c2n4; float c2p1 = 0.f, c2n1 = 0.f;
    unsigned bw;
    unsigned u[PV];

    auto load_jside = [&](int j0) {
        if constexpr (NH == 4) {
            c2p4 = *(const float4*)&e2p[ph * NN + j0 + pcq];
            c2n4 = *(const float4*)&e2n[ph * NN + j0 + pcq];
        } else {
            c2p1 = e2p[j0 + pcq]; c2n1 = e2n[j0 + pcq];
        }
        bw = g_adjbits[(row0 + pr) * (NN / 32) + j0 / 32];
    };
    auto compute_p = [&]() {
        if constexpr (NH == 4) {
            float e2pv[4] = {c2p4.x, c2p4.y, c2p4.z, c2p4.w};
            float e2nv[4] = {c2n4.x, c2n4.y, c2n4.z, c2n4.w};
#pragma unroll
            for (int i = 0; i < 4; i++) {
                float pm = fmaxf(E1pv * e2pv[i], E1nv * e2nv[i]);
                float p  = ((bw >> (pcq + i)) & 1u) ? pm : 0.0f;
                u[i] = cvt_tf32(p);
            }
        } else {
            float pm = fmaxf(E1pv * c2p1, E1nv * c2n1);
            float p  = ((bw >> pcq) & 1u) ? pm : 0.0f;
            u[0] = cvt_tf32(p);
        }
    };

    // prologue: p(0) regs, j-side(1) prefetched
    load_jside(0);
    compute_p();
    if (NT > 1) load_jside(TJ);

    for (int t = 0; t < NT; t++) {
        __syncthreads();               // mma(t-1) done with p_s AND wh_s
        // store p(t) + denominator
        if constexpr (NH == 4) {
            uint4 pu; pu.x = u[0]; pu.y = u[1]; pu.z = u[2]; pu.w = u[3];
            *(uint4*)&p_s[(ph * 16 + pr) * 36 + pcq] = pu;
            dsum += __uint_as_float(u[0]) + __uint_as_float(u[1])
                  + __uint_as_float(u[2]) + __uint_as_float(u[3]);
        } else {
            p_s[pr * 36 + pcq] = __uint_as_float(u[0]);
            dsum += __uint_as_float(u[0]);
        }
        // stage wh(t) into the single buffer (mma(t-1) finished with it)
        issue_wh(t * TJ);
        // overlap cp latency with p(t+1) compute + j-side(t+2) prefetch
        if (t + 1 < NT) {
            compute_p();
            if (t + 2 < NT) load_jside((t + 2) * TJ);
        }
        cp_wait<0>();
        __syncthreads();               // p_s + wh(t) visible
        // mma(t)
        const float* pa = &p_s[hw * 16 * 36];
#pragma unroll
        for (int ks = 0; ks < 4; ks++) {
            unsigned a0 = __float_as_uint(pa[g * 36 + 8 * ks + c]);
            unsigned a1 = __float_as_uint(pa[(g + 8) * 36 + 8 * ks + c]);
            unsigned a2 = __float_as_uint(pa[g * 36 + 8 * ks + c + 4]);
            unsigned a3 = __float_as_uint(pa[(g + 8) * 36 + 8 * ks + c + 4]);
#pragma unroll
            for (int q = 0; q < CHUNKS; q++) {
                int feat = warp * (8 * CHUNKS) + q * 8 + g;
                unsigned b0 = __float_as_uint(wh_s[(8 * ks + c) * WS + feat]);
                unsigned b1 = __float_as_uint(wh_s[(8 * ks + c + 4) * WS + feat]);
                mma_tf32(d[q], a0, a1, a2, a3, b0, b1);
            }
        }
    }

    // ---- denominator reduce + publish ----
    __syncthreads();
    if constexpr (NH == 4) {
        dsum += __shfl_xor_sync(0xffffffffu, dsum, 1);
        dsum += __shfl_xor_sync(0xffffffffu, dsum, 2);
        dsum += __shfl_xor_sync(0xffffffffu, dsum, 4);
        if ((tid & 7) == 0) denom_s[ph * 16 + pr] = dsum;
    } else {
#pragma unroll
        for (int off = 16; off; off >>= 1)
            dsum += __shfl_xor_sync(0xffffffffu, dsum, off);
        if (lane == 0) denom_s[pr] = dsum;
    }
    __syncthreads();

    // ---- normalize + ELU + store ----
    const float inv1 = 1.0f / denom_s[hw * 16 + g];
    const float inv2 = 1.0f / denom_s[hw * 16 + g + 8];
#pragma unroll
    for (int q = 0; q < CHUNKS; q++) {
        int feat = warp * (8 * CHUNKS) + q * 8 + 2 * c;
        float v0 = d[q][0] * inv1, v1 = d[q][1] * inv1;
        float v2 = d[q][2] * inv2, v3 = d[q][3] * inv2;
        v0 = v0 > 0.0f ? v0 : expm1f(v0);
        v1 = v1 > 0.0f ? v1 : expm1f(v1);
        v2 = v2 > 0.0f ? v2 : expm1f(v2);
        v3 = v3 > 0.0f ? v3 : expm1f(v3);
        *(float2*)&out[(row0 + g) * F + feat]     = make_float2(v0, v1);
        *(float2*)&out[(row0 + g + 8) * F + feat] = make_float2(v2, v3);
    }
}

__global__ void __launch_bounds__(512, 2) attn1_k() {
    attn_body<F1T, NH1>(g_Wh1, g_e1p_h, g_e1n_h, g_e2p_h, g_e2n_h, g_h1);
}
__global__ void __launch_bounds__(512, 2) attn2_k(float* __restrict__ out) {
    attn_body<F2T, 1>(g_Wh2, g_e1p_o, g_e1n_o, g_e2p_o, g_e2n_o, out);
}

// =======================================================================
extern "C" void kernel_launch(void* const* d_in, const int* in_sizes, int n_in,
                              void* d_out, int out_size) {
    const float* x       = (const float*)d_in[0];
    const int*   adj     = (const int*)  d_in[1];
    const float* W_heads = (const float*)d_in[2];
    const float* a_heads = (const float*)d_in[3];
    const float* W_out   = (const float*)d_in[4];
    const float* a_out   = (const float*)d_in[5];
    float* out = (float*)d_out;

    adjbits_k<<<NN, 128>>>(adj);
    gemm1_k<<<NN / 32, 512>>>(x, W_heads);
    fvec1_k<<<NN, 64>>>(a_heads);
    attn1_k<<<NN / 16, 512>>>();
    gemm2_k<<<NN / 32, 512>>>(W_out);
    fvec2_k<<<NN, 128>>>(a_out);
    attn2_k<<<NN / 16, 512>>>(out);
}

// round 16
// speedup vs baseline: 2.5418x; 1.3440x over previous
#include <cuda_runtime.h>

#define NN   4096
#define IND  256
#define HID1 64
#define NH1  4
#define F1T  256
#define F2T  128

typedef unsigned long long u64;

// ---- scratch (device globals; no allocation allowed) ----
__device__ float g_Wh1[NN * F1T];          // tf32-rounded
__device__ float g_h1 [NN * F1T];
__device__ float g_Wh2[NN * F2T];          // tf32-rounded
__device__ float g_e1p_h[NH1 * NN], g_e1n_h[NH1 * NN];
__device__ float g_e2p_h[NH1 * NN], g_e2n_h[NH1 * NN];
__device__ float g_e1p_o[NN], g_e1n_o[NN], g_e2p_o[NN], g_e2n_o[NN];
__device__ unsigned g_adjbits[NN * (NN / 32)];
__device__ float g_np1[2 * NN * F1T];      // attn1 numerator partials (8MB)
__device__ float g_dp1[2 * NH1 * NN];
__device__ float g_np2[2 * NN * F2T];      // attn2 numerator partials (4MB)
__device__ float g_dp2[2 * NN];

// ---- packed fp32x2 helpers ----
__device__ __forceinline__ u64 pack2(float lo, float hi) {
    return (u64)__float_as_uint(lo) | ((u64)__float_as_uint(hi) << 32);
}
__device__ __forceinline__ float lo2(u64 v) { return __uint_as_float((unsigned)v); }
__device__ __forceinline__ float hi2(u64 v) { return __uint_as_float((unsigned)(v >> 32)); }
__device__ __forceinline__ u64 fma2(u64 a, u64 b, u64 c) {
    u64 d;
    asm("fma.rn.f32x2 %0, %1, %2, %3;" : "=l"(d) : "l"(a), "l"(b), "l"(c));
    return d;
}
__device__ __forceinline__ unsigned cvt_tf32(float x) {
    unsigned u;
    asm("cvt.rna.tf32.f32 %0, %1;" : "=r"(u) : "f"(x));
    return u;
}
__device__ __forceinline__ void mma_tf32(float d[4],
        unsigned a0, unsigned a1, unsigned a2, unsigned a3,
        unsigned b0, unsigned b1) {
    asm volatile(
        "mma.sync.aligned.m16n8k8.row.col.f32.tf32.tf32.f32 "
        "{%0,%1,%2,%3}, {%4,%5,%6,%7}, {%8,%9}, {%0,%1,%2,%3};"
        : "+f"(d[0]), "+f"(d[1]), "+f"(d[2]), "+f"(d[3])
        : "r"(a0), "r"(a1), "r"(a2), "r"(a3), "r"(b0), "r"(b1));
}
__device__ __forceinline__ unsigned sptr(const void* p) {
    return (unsigned)__cvta_generic_to_shared(p);
}
__device__ __forceinline__ void cp16(unsigned dst, const void* src) {
    asm volatile("cp.async.ca.shared.global [%0], [%1], 16;" :: "r"(dst), "l"(src) : "memory");
}
__device__ __forceinline__ void cp4(unsigned dst, const void* src) {
    asm volatile("cp.async.ca.shared.global [%0], [%1], 4;" :: "r"(dst), "l"(src) : "memory");
}
__device__ __forceinline__ void cp_commit() {
    asm volatile("cp.async.commit_group;" ::: "memory");
}
template <int N>
__device__ __forceinline__ void cp_wait() {
    asm volatile("cp.async.wait_group %0;" :: "n"(N) : "memory");
}

// =======================================================================
// adj bit-pack
// =======================================================================
__global__ void adjbits_k(const int* __restrict__ adj) {
    const int row  = blockIdx.x;
    const int w    = threadIdx.x >> 5;
    const int lane = threadIdx.x & 31;
#pragma unroll 4
    for (int k = 0; k < 32; k++) {
        int col = w * 1024 + k * 32 + lane;
        unsigned m = __ballot_sync(0xffffffffu, adj[row * NN + col] > 0);
        if (lane == 0) g_adjbits[row * (NN / 32) + w * 32 + k] = m;
    }
}

// =======================================================================
// GEMM (proven): C = A[4096,256] @ B, output tf32-rounded
// =======================================================================
template <int FCOLS, bool HEADS_B>
__device__ __forceinline__ void gemm_body(const float* __restrict__ A,
                                          const float* __restrict__ B,
                                          float* __restrict__ C) {
    constexpr int K = 256, XPAD = 36, FPT = FCOLS / 64;
    constexpr int NCB = 32 * FCOLS / 2048;
    const int tid   = threadIdx.x;
    const int feat0 = (tid & 63) * FPT;
    const int r0    = (tid >> 6) * 4;
    const int row0  = blockIdx.x * 32;

    __shared__ __align__(16) float x_s[2][32 * XPAD];
    __shared__ __align__(16) float b_s[2][32 * FCOLS];

    auto issue_tile = [&](int buf, int k0) {
#pragma unroll
        for (int i = 0; i < 2; i++) {
            int e = i * 512 + tid;
            int r = e & 31, kk = e >> 5;
            cp4(sptr(&x_s[buf][kk * XPAD + r]), &A[(row0 + r) * K + k0 + kk]);
        }
#pragma unroll
        for (int c = 0; c < NCB; c++) {
            int flat = c * 2048 + tid * 4;
            int kk = flat / FCOLS, feat = flat % FCOLS;
            const float* src = HEADS_B
                ? &B[(feat >> 6) * (IND * HID1) + (k0 + kk) * HID1 + (feat & 63)]
                : &B[(k0 + kk) * FCOLS + feat];
            cp16(sptr(&b_s[buf][flat]), src);
        }
        cp_commit();
    };

    u64 acc[FPT][2];
#pragma unroll
    for (int f = 0; f < FPT; f++) { acc[f][0] = 0ull; acc[f][1] = 0ull; }

    issue_tile(0, 0);
    for (int t = 0; t < K / 32; t++) {
        if (t + 1 < K / 32) { issue_tile((t + 1) & 1, (t + 1) * 32); cp_wait<1>(); }
        else                { cp_wait<0>(); }
        __syncthreads();
        const float* xs = x_s[t & 1];
        const float* bs = b_s[t & 1];
#pragma unroll 8
        for (int kk = 0; kk < 32; kk++) {
            ulonglong2 pv = *(const ulonglong2*)&xs[kk * XPAD + r0];
            float wv[FPT];
            if constexpr (FPT == 4) {
                float4 v = *(const float4*)&bs[kk * FCOLS + feat0];
                wv[0] = v.x; wv[1] = v.y; wv[2] = v.z; wv[3] = v.w;
            } else {
                float2 v = *(const float2*)&bs[kk * FCOLS + feat0];
                wv[0] = v.x; wv[1] = v.y;
            }
#pragma unroll
            for (int f = 0; f < FPT; f++) {
                u64 w2 = pack2(wv[f], wv[f]);
                acc[f][0] = fma2(pv.x, w2, acc[f][0]);
                acc[f][1] = fma2(pv.y, w2, acc[f][1]);
            }
        }
        __syncthreads();
    }
#pragma unroll
    for (int i = 0; i < 4; i++) {
        float v[FPT];
#pragma unroll
        for (int f = 0; f < FPT; f++) {
            float raw = (i & 1) ? hi2(acc[f][i >> 1]) : lo2(acc[f][i >> 1]);
            v[f] = __uint_as_float(cvt_tf32(raw));
        }
        float* cp = &C[(row0 + r0 + i) * FCOLS + feat0];
        if constexpr (FPT == 4) *(float4*)cp = make_float4(v[0], v[1], v[2], v[3]);
        else                    *(float2*)cp = make_float2(v[0], v[1]);
    }
}

__global__ void __launch_bounds__(512, 1) gemm1_k(const float* __restrict__ x,
                                                  const float* __restrict__ W_heads) {
    gemm_body<F1T, true>(x, W_heads, g_Wh1);
}
__global__ void __launch_bounds__(512, 1) gemm2_k(const float* __restrict__ W_out) {
    gemm_body<F2T, false>(g_h1, W_out, g_Wh2);
}

// =======================================================================
// f-vector kernels (factored exp)
// =======================================================================
__global__ void fvec1_k(const float* __restrict__ a_heads) {
    const int i = blockIdx.x;
    const int t = threadIdx.x;
    const int lane = t & 31, w = t >> 5;
    float p1[NH1], p2[NH1];
#pragma unroll
    for (int h = 0; h < NH1; h++) {
        float v = g_Wh1[i * F1T + h * HID1 + t];
        p1[h] = v * a_heads[h * (2 * HID1) + t];
        p2[h] = v * a_heads[h * (2 * HID1) + HID1 + t];
    }
#pragma unroll
    for (int off = 16; off; off >>= 1)
#pragma unroll
        for (int h = 0; h < NH1; h++) {
            p1[h] += __shfl_down_sync(0xffffffffu, p1[h], off);
            p2[h] += __shfl_down_sync(0xffffffffu, p2[h], off);
        }
    __shared__ float red[2][2 * NH1];
    if (lane == 0) {
#pragma unroll
        for (int h = 0; h < NH1; h++) { red[w][h] = p1[h]; red[w][NH1 + h] = p2[h]; }
    }
    __syncthreads();
    if (t == 0) {
#pragma unroll
        for (int h = 0; h < NH1; h++) {
            float f1 = red[0][h] + red[1][h];
            float f2 = red[0][NH1 + h] + red[1][NH1 + h];
            g_e1p_h[h * NN + i] = __expf(f1);
            g_e1n_h[h * NN + i] = __expf(0.5f * f1);
            g_e2p_h[h * NN + i] = __expf(f2);
            g_e2n_h[h * NN + i] = __expf(0.5f * f2);
        }
    }
}

__global__ void fvec2_k(const float* __restrict__ a_out) {
    const int i = blockIdx.x;
    const int t = threadIdx.x;
    const int lane = t & 31, w = t >> 5;
    float v  = g_Wh2[i * F2T + t];
    float p1 = v * a_out[t];
    float p2 = v * a_out[F2T + t];
#pragma unroll
    for (int off = 16; off; off >>= 1) {
        p1 += __shfl_down_sync(0xffffffffu, p1, off);
        p2 += __shfl_down_sync(0xffffffffu, p2, off);
    }
    __shared__ float red[4][2];
    if (lane == 0) { red[w][0] = p1; red[w][1] = p2; }
    __syncthreads();
    if (t == 0) {
        float f1 = red[0][0] + red[1][0] + red[2][0] + red[3][0];
        float f2 = red[0][1] + red[1][1] + red[2][1] + red[3][1];
        g_e1p_o[i] = __expf(f1);
        g_e1n_o[i] = __expf(0.5f * f1);
        g_e2p_o[i] = __expf(f2);
        g_e2n_o[i] = __expf(0.5f * f2);
    }
}

// =======================================================================
// tf32 mma.sync attention, 32-row blocks + 2-way split-J, occ 2.
// grid = (NN/32)*2 = 256; block 512 thr. blockIdx: rowblk = bid>>1,
// split = bid&1 handles j in [split*2048, split*2048+2048).
// 16 warps = 2 rowgroups x 8 featgroups (CHUNKS = F/64 n8-chunks each).
// Per 32-j tile: sync -> compute p direct -> STS -> issue wh -> wait+sync
// -> mma. Partial numerator (TMEM-free) + fp32 denominators to global;
// red kernels finish (sum splits, divide, ELU).
// =======================================================================
template <int F, int NH>
__device__ __forceinline__ void attn_body(const float* __restrict__ Wh,
                                          const float* __restrict__ e1p,
                                          const float* __restrict__ e1n,
                                          const float* __restrict__ e2p,
                                          const float* __restrict__ e2n,
                                          float* __restrict__ npart,
                                          float* __restrict__ dpart) {
    constexpr int TJ = 32, NT = NN / 2 / TJ;     // 64 tiles per split
    constexpr int WS = F + 8;                    // 264 / 136
    constexpr int CHUNKS = F / 64;               // 4 / 2
    constexpr int NCW = (TJ * F / 4) / 512;      // cp16 per thread
    const int tid  = threadIdx.x;
    const int lane = tid & 31, warp = tid >> 5;
    const int g = lane >> 2, c = lane & 3;
    const int rowblk = (int)blockIdx.x >> 1, split = (int)blockIdx.x & 1;
    const int row0 = rowblk * 32;
    const int jbase = split * (NN / 2);
    const int rg = warp >> 3;                    // rowgroup of mma warp
    const int feat0 = (warp & 7) * (F / 8);
    const int hw = feat0 / (F / NH);             // head of mma warp

    __shared__ __align__(16) float p_s[2][NH * 16 * 36];   // [rg][h][r][36]
    __shared__ __align__(16) float wh_s[TJ * WS];          // single buffer

    auto issue_wh = [&](int j0) {
#pragma unroll
        for (int cc = 0; cc < NCW; cc++) {
            int fc = cc * 512 + tid;
            int k = fc / (F / 4), off = (fc % (F / 4)) * 4;
            cp16(sptr(&wh_s[k * WS + off]), &Wh[(j0 + k) * F + off]);
        }
        cp_commit();
    };

    float d[CHUNKS][4];
#pragma unroll
    for (int q = 0; q < CHUNKS; q++)
#pragma unroll
        for (int i = 0; i < 4; i++) d[q][i] = 0.0f;

    // p-compute role
    int ph, pr, pcq;
    if constexpr (NH == 4) { ph = tid >> 7; pr = (tid >> 3) & 15; pcq = (tid & 7) << 2; }
    else                   { ph = 0;        pr = tid >> 4;        pcq = (tid & 15) << 1; }
    float E1pv0, E1nv0, E1pv1, E1nv1, dsum0 = 0.0f, dsum1 = 0.0f;
    if constexpr (NH == 4) {
        E1pv0 = e1p[ph * NN + row0 + pr];       E1nv0 = e1n[ph * NN + row0 + pr];
        E1pv1 = e1p[ph * NN + row0 + 16 + pr];  E1nv1 = e1n[ph * NN + row0 + 16 + pr];
    } else {
        E1pv0 = e1p[row0 + pr];                 E1nv0 = e1n[row0 + pr];
        E1pv1 = 0.f; E1nv1 = 0.f;
    }

    for (int t = 0; t < NT; t++) {
        const int j0 = jbase + t * TJ;
        __syncthreads();               // mma(t-1) done with p_s and wh_s
        issue_wh(j0);
        // ---- p phase (direct; latency covered by co-resident block) ----
        if constexpr (NH == 4) {
            float4 q2p = *(const float4*)&e2p[ph * NN + j0 + pcq];
            float4 q2n = *(const float4*)&e2n[ph * NN + j0 + pcq];
            float ap[4] = {q2p.x, q2p.y, q2p.z, q2p.w};
            float an[4] = {q2n.x, q2n.y, q2n.z, q2n.w};
            {
                unsigned bw = g_adjbits[(row0 + pr) * (NN / 32) + (j0 >> 5)];
                float pv[4];
#pragma unroll
                for (int i = 0; i < 4; i++) {
                    float pm = fmaxf(E1pv0 * ap[i], E1nv0 * an[i]);
                    float p  = ((bw >> (pcq + i)) & 1u) ? pm : 0.0f;
                    pv[i] = __uint_as_float(cvt_tf32(p));
                    dsum0 += pv[i];
                }
                *(float4*)&p_s[0][(ph * 16 + pr) * 36 + pcq] =
                    make_float4(pv[0], pv[1], pv[2], pv[3]);
            }
            {
                unsigned bw = g_adjbits[(row0 + 16 + pr) * (NN / 32) + (j0 >> 5)];
                float pv[4];
#pragma unroll
                for (int i = 0; i < 4; i++) {
                    float pm = fmaxf(E1pv1 * ap[i], E1nv1 * an[i]);
                    float p  = ((bw >> (pcq + i)) & 1u) ? pm : 0.0f;
                    pv[i] = __uint_as_float(cvt_tf32(p));
                    dsum1 += pv[i];
                }
                *(float4*)&p_s[1][(ph * 16 + pr) * 36 + pcq] =
                    make_float4(pv[0], pv[1], pv[2], pv[3]);
            }
        } else {
            float2 q2p = *(const float2*)&e2p[j0 + pcq];
            float2 q2n = *(const float2*)&e2n[j0 + pcq];
            unsigned bw = g_adjbits[(row0 + pr) * (NN / 32) + (j0 >> 5)];
            float p0 = fmaxf(E1pv0 * q2p.x, E1nv0 * q2n.x);
            float p1 = fmaxf(E1pv0 * q2p.y, E1nv0 * q2n.y);
            p0 = ((bw >> pcq) & 1u) ? p0 : 0.0f;
            p1 = ((bw >> (pcq + 1)) & 1u) ? p1 : 0.0f;
            p0 = __uint_as_float(cvt_tf32(p0));
            p1 = __uint_as_float(cvt_tf32(p1));
            dsum0 += p0 + p1;
            *(float2*)&p_s[pr >> 4][(pr & 15) * 36 + pcq] = make_float2(p0, p1);
        }
        cp_wait<0>();
        __syncthreads();               // p_s + wh visible
        // ---- mma ----
        const float* pa = &p_s[rg][hw * 16 * 36];
#pragma unroll
        for (int ks = 0; ks < 4; ks++) {
            unsigned a0 = __float_as_uint(pa[g * 36 + 8 * ks + c]);
            unsigned a1 = __float_as_uint(pa[(g + 8) * 36 + 8 * ks + c]);
            unsigned a2 = __float_as_uint(pa[g * 36 + 8 * ks + c + 4]);
            unsigned a3 = __float_as_uint(pa[(g + 8) * 36 + 8 * ks + c + 4]);
#pragma unroll
            for (int q = 0; q < CHUNKS; q++) {
                int feat = feat0 + q * 8 + g;
                unsigned b0 = __float_as_uint(wh_s[(8 * ks + c) * WS + feat]);
                unsigned b1 = __float_as_uint(wh_s[(8 * ks + c + 4) * WS + feat]);
                mma_tf32(d[q], a0, a1, a2, a3, b0, b1);
            }
        }
    }

    // ---- denominator partials -> global ----
    if constexpr (NH == 4) {
        dsum0 += __shfl_xor_sync(0xffffffffu, dsum0, 1);
        dsum0 += __shfl_xor_sync(0xffffffffu, dsum0, 2);
        dsum0 += __shfl_xor_sync(0xffffffffu, dsum0, 4);
        dsum1 += __shfl_xor_sync(0xffffffffu, dsum1, 1);
        dsum1 += __shfl_xor_sync(0xffffffffu, dsum1, 2);
        dsum1 += __shfl_xor_sync(0xffffffffu, dsum1, 4);
        if ((lane & 7) == 0) {
            dpart[(split * NH1 + ph) * NN + row0 + pr]      = dsum0;
            dpart[(split * NH1 + ph) * NN + row0 + 16 + pr] = dsum1;
        }
    } else {
        dsum0 += __shfl_xor_sync(0xffffffffu, dsum0, 1);
        dsum0 += __shfl_xor_sync(0xffffffffu, dsum0, 2);
        dsum0 += __shfl_xor_sync(0xffffffffu, dsum0, 4);
        dsum0 += __shfl_xor_sync(0xffffffffu, dsum0, 8);
        if ((lane & 15) == 0) dpart[split * NN + row0 + pr] = dsum0;
    }

    // ---- numerator partials -> global ----
    const int orow = row0 + rg * 16;
#pragma unroll
    for (int q = 0; q < CHUNKS; q++) {
        int feat = feat0 + q * 8 + 2 * c;
        *(float2*)&npart[(split * NN + orow + g) * F + feat]     = make_float2(d[q][0], d[q][1]);
        *(float2*)&npart[(split * NN + orow + g + 8) * F + feat] = make_float2(d[q][2], d[q][3]);
    }
}

__global__ void __launch_bounds__(512, 2) attn1_k() {
    attn_body<F1T, NH1>(g_Wh1, g_e1p_h, g_e1n_h, g_e2p_h, g_e2n_h, g_np1, g_dp1);
}
__global__ void __launch_bounds__(512, 2) attn2_k() {
    attn_body<F2T, 1>(g_Wh2, g_e1p_o, g_e1n_o, g_e2p_o, g_e2n_o, g_np2, g_dp2);
}

// =======================================================================
// split-J reductions: sum 2 partials, divide, ELU
// =======================================================================
__global__ void red1_k() {
    const int i = blockIdx.x, f = threadIdx.x;
    const int h = f >> 6;
    float num = g_np1[i * F1T + f] + g_np1[(NN + i) * F1T + f];
    float den = g_dp1[h * NN + i] + g_dp1[(NH1 + h) * NN + i];
    float v = num / den;
    g_h1[i * F1T + f] = v > 0.0f ? v : expm1f(v);
}
__global__ void red2_k(float* __restrict__ out) {
    const int i = blockIdx.x, f = threadIdx.x;
    float num = g_np2[i * F2T + f] + g_np2[(NN + i) * F2T + f];
    float den = g_dp2[i] + g_dp2[NN + i];
    float v = num / den;
    out[i * F2T + f] = v > 0.0f ? v : expm1f(v);
}

// =======================================================================
extern "C" void kernel_launch(void* const* d_in, const int* in_sizes, int n_in,
                              void* d_out, int out_size) {
    const float* x       = (const float*)d_in[0];
    const int*   adj     = (const int*)  d_in[1];
    const float* W_heads = (const float*)d_in[2];
    const float* a_heads = (const float*)d_in[3];
    const float* W_out   = (const float*)d_in[4];
    const float* a_out   = (const float*)d_in[5];
    float* out = (float*)d_out;

    adjbits_k<<<NN, 128>>>(adj);
    gemm1_k<<<NN / 32, 512>>>(x, W_heads);
    fvec1_k<<<NN, 64>>>(a_heads);
    attn1_k<<<(NN / 32) * 2, 512>>>();
    red1_k<<<NN, F1T>>>();
    gemm2_k<<<NN / 32, 512>>>(W_out);
    fvec2_k<<<NN, 128>>>(a_out);
    attn2_k<<<(NN / 32) * 2, 512>>>();
    red2_k<<<NN, F2T>>>(out);
}

// round 17
// speedup vs baseline: 3.1457x; 1.2376x over previous
#include <cuda_runtime.h>
#include <cuda_fp16.h>

#define NN   4096
#define IND  256
#define HID1 64
#define NH1  4
#define F1T  256
#define F2T  128

typedef unsigned long long u64;

// ---- scratch (device globals; no allocation allowed) ----
__device__ float  g_Wh1[NN * F1T];            // fp32 row-major (fvec)
__device__ __half g_Wh1Th[F1T * NN];          // fp16 transposed [feat][row] (attn B)
__device__ float  g_h1 [NN * F1T];
__device__ float  g_Wh2[NN * F2T];
__device__ __half g_Wh2Th[F2T * NN];
__device__ float g_e1p_h[NH1 * NN], g_e1n_h[NH1 * NN];
__device__ float g_e2p_h[NH1 * NN], g_e2n_h[NH1 * NN];
__device__ float g_e1p_o[NN], g_e1n_o[NN], g_e2p_o[NN], g_e2n_o[NN];
__device__ unsigned g_adjbits[NN * (NN / 32)];
__device__ float g_np1[2 * NN * F1T];
__device__ float g_dp1[2 * NH1 * NN];
__device__ float g_np2[2 * NN * F2T];
__device__ float g_dp2[2 * NN];

// ---- packed fp32x2 helpers ----
__device__ __forceinline__ u64 pack2(float lo, float hi) {
    return (u64)__float_as_uint(lo) | ((u64)__float_as_uint(hi) << 32);
}
__device__ __forceinline__ float lo2(u64 v) { return __uint_as_float((unsigned)v); }
__device__ __forceinline__ float hi2(u64 v) { return __uint_as_float((unsigned)(v >> 32)); }
__device__ __forceinline__ u64 fma2(u64 a, u64 b, u64 c) {
    u64 d;
    asm("fma.rn.f32x2 %0, %1, %2, %3;" : "=l"(d) : "l"(a), "l"(b), "l"(c));
    return d;
}
// ---- fp16 mma (m16n8k16, fp32 accum) ----
__device__ __forceinline__ void mma_f16(float d[4],
        unsigned a0, unsigned a1, unsigned a2, unsigned a3,
        unsigned b0, unsigned b1) {
    asm volatile(
        "mma.sync.aligned.m16n8k16.row.col.f32.f16.f16.f32 "
        "{%0,%1,%2,%3}, {%4,%5,%6,%7}, {%8,%9}, {%0,%1,%2,%3};"
        : "+f"(d[0]), "+f"(d[1]), "+f"(d[2]), "+f"(d[3])
        : "r"(a0), "r"(a1), "r"(a2), "r"(a3), "r"(b0), "r"(b1));
}
__device__ __forceinline__ unsigned sptr(const void* p) {
    return (unsigned)__cvta_generic_to_shared(p);
}
__device__ __forceinline__ void cp16(unsigned dst, const void* src) {
    asm volatile("cp.async.ca.shared.global [%0], [%1], 16;" :: "r"(dst), "l"(src) : "memory");
}
__device__ __forceinline__ void cp4(unsigned dst, const void* src) {
    asm volatile("cp.async.ca.shared.global [%0], [%1], 4;" :: "r"(dst), "l"(src) : "memory");
}
__device__ __forceinline__ void cp_commit() {
    asm volatile("cp.async.commit_group;" ::: "memory");
}
template <int N>
__device__ __forceinline__ void cp_wait() {
    asm volatile("cp.async.wait_group %0;" :: "n"(N) : "memory");
}

// =======================================================================
// adj bit-pack
// =======================================================================
__global__ void adjbits_k(const int* __restrict__ adj) {
    const int row  = blockIdx.x;
    const int w    = threadIdx.x >> 5;
    const int lane = threadIdx.x & 31;
#pragma unroll 4
    for (int k = 0; k < 32; k++) {
        int col = w * 1024 + k * 32 + lane;
        unsigned m = __ballot_sync(0xffffffffu, adj[row * NN + col] > 0);
        if (lane == 0) g_adjbits[row * (NN / 32) + w * 32 + k] = m;
    }
}

// =======================================================================
// GEMM (proven): C = A[4096,256] @ B
// outputs: fp32 row-major C + fp16 transposed CTh [feat][row]
// =======================================================================
template <int FCOLS, bool HEADS_B>
__device__ __forceinline__ void gemm_body(const float* __restrict__ A,
                                          const float* __restrict__ B,
                                          float* __restrict__ C,
                                          __half* __restrict__ CTh) {
    constexpr int K = 256, XPAD = 36, FPT = FCOLS / 64;
    constexpr int NCB = 32 * FCOLS / 2048;
    const int tid   = threadIdx.x;
    const int feat0 = (tid & 63) * FPT;
    const int r0    = (tid >> 6) * 4;
    const int row0  = blockIdx.x * 32;

    __shared__ __align__(16) float x_s[2][32 * XPAD];
    __shared__ __align__(16) float b_s[2][32 * FCOLS];

    auto issue_tile = [&](int buf, int k0) {
#pragma unroll
        for (int i = 0; i < 2; i++) {
            int e = i * 512 + tid;
            int r = e & 31, kk = e >> 5;
            cp4(sptr(&x_s[buf][kk * XPAD + r]), &A[(row0 + r) * K + k0 + kk]);
        }
#pragma unroll
        for (int c = 0; c < NCB; c++) {
            int flat = c * 2048 + tid * 4;
            int kk = flat / FCOLS, feat = flat % FCOLS;
            const float* src = HEADS_B
                ? &B[(feat >> 6) * (IND * HID1) + (k0 + kk) * HID1 + (feat & 63)]
                : &B[(k0 + kk) * FCOLS + feat];
            cp16(sptr(&b_s[buf][flat]), src);
        }
        cp_commit();
    };

    u64 acc[FPT][2];
#pragma unroll
    for (int f = 0; f < FPT; f++) { acc[f][0] = 0ull; acc[f][1] = 0ull; }

    issue_tile(0, 0);
    for (int t = 0; t < K / 32; t++) {
        if (t + 1 < K / 32) { issue_tile((t + 1) & 1, (t + 1) * 32); cp_wait<1>(); }
        else                { cp_wait<0>(); }
        __syncthreads();
        const float* xs = x_s[t & 1];
        const float* bs = b_s[t & 1];
#pragma unroll 8
        for (int kk = 0; kk < 32; kk++) {
            ulonglong2 pv = *(const ulonglong2*)&xs[kk * XPAD + r0];
            float wv[FPT];
            if constexpr (FPT == 4) {
                float4 v = *(const float4*)&bs[kk * FCOLS + feat0];
                wv[0] = v.x; wv[1] = v.y; wv[2] = v.z; wv[3] = v.w;
            } else {
                float2 v = *(const float2*)&bs[kk * FCOLS + feat0];
                wv[0] = v.x; wv[1] = v.y;
            }
#pragma unroll
            for (int f = 0; f < FPT; f++) {
                u64 w2 = pack2(wv[f], wv[f]);
                acc[f][0] = fma2(pv.x, w2, acc[f][0]);
                acc[f][1] = fma2(pv.y, w2, acc[f][1]);
            }
        }
        __syncthreads();
    }
    float vv[4][FPT];
#pragma unroll
    for (int i = 0; i < 4; i++)
#pragma unroll
        for (int f = 0; f < FPT; f++)
            vv[i][f] = (i & 1) ? hi2(acc[f][i >> 1]) : lo2(acc[f][i >> 1]);
#pragma unroll
    for (int i = 0; i < 4; i++) {
        float* cp = &C[(row0 + r0 + i) * FCOLS + feat0];
        if constexpr (FPT == 4) *(float4*)cp = make_float4(vv[i][0], vv[i][1], vv[i][2], vv[i][3]);
        else                    *(float2*)cp = make_float2(vv[i][0], vv[i][1]);
    }
#pragma unroll
    for (int f = 0; f < FPT; f++) {
        __half hh[4];
#pragma unroll
        for (int i = 0; i < 4; i++) hh[i] = __float2half_rn(vv[i][f]);
        *(uint2*)&CTh[(feat0 + f) * NN + row0 + r0] = *(uint2*)hh;
    }
}

__global__ void __launch_bounds__(512, 1) gemm1_k(const float* __restrict__ x,
                                                  const float* __restrict__ W_heads) {
    gemm_body<F1T, true>(x, W_heads, g_Wh1, g_Wh1Th);
}
__global__ void __launch_bounds__(512, 1) gemm2_k(const float* __restrict__ W_out) {
    gemm_body<F2T, false>(g_h1, W_out, g_Wh2, g_Wh2Th);
}

// =======================================================================
// f-vector kernels (factored exp)
// =======================================================================
__global__ void fvec1_k(const float* __restrict__ a_heads) {
    const int i = blockIdx.x;
    const int t = threadIdx.x;
    const int lane = t & 31, w = t >> 5;
    float p1[NH1], p2[NH1];
#pragma unroll
    for (int h = 0; h < NH1; h++) {
        float v = g_Wh1[i * F1T + h * HID1 + t];
        p1[h] = v * a_heads[h * (2 * HID1) + t];
        p2[h] = v * a_heads[h * (2 * HID1) + HID1 + t];
    }
#pragma unroll
    for (int off = 16; off; off >>= 1)
#pragma unroll
        for (int h = 0; h < NH1; h++) {
            p1[h] += __shfl_down_sync(0xffffffffu, p1[h], off);
            p2[h] += __shfl_down_sync(0xffffffffu, p2[h], off);
        }
    __shared__ float red[2][2 * NH1];
    if (lane == 0) {
#pragma unroll
        for (int h = 0; h < NH1; h++) { red[w][h] = p1[h]; red[w][NH1 + h] = p2[h]; }
    }
    __syncthreads();
    if (t == 0) {
#pragma unroll
        for (int h = 0; h < NH1; h++) {
            float f1 = red[0][h] + red[1][h];
            float f2 = red[0][NH1 + h] + red[1][NH1 + h];
            g_e1p_h[h * NN + i] = __expf(f1);
            g_e1n_h[h * NN + i] = __expf(0.5f * f1);
            g_e2p_h[h * NN + i] = __expf(f2);
            g_e2n_h[h * NN + i] = __expf(0.5f * f2);
        }
    }
}

__global__ void fvec2_k(const float* __restrict__ a_out) {
    const int i = blockIdx.x;
    const int t = threadIdx.x;
    const int lane = t & 31, w = t >> 5;
    float v  = g_Wh2[i * F2T + t];
    float p1 = v * a_out[t];
    float p2 = v * a_out[F2T + t];
#pragma unroll
    for (int off = 16; off; off >>= 1) {
        p1 += __shfl_down_sync(0xffffffffu, p1, off);
        p2 += __shfl_down_sync(0xffffffffu, p2, off);
    }
    __shared__ float red[4][2];
    if (lane == 0) { red[w][0] = p1; red[w][1] = p2; }
    __syncthreads();
    if (t == 0) {
        float f1 = red[0][0] + red[1][0] + red[2][0] + red[3][0];
        float f2 = red[0][1] + red[1][1] + red[2][1] + red[3][1];
        g_e1p_o[i] = __expf(f1);
        g_e1n_o[i] = __expf(0.5f * f1);
        g_e2p_o[i] = __expf(f2);
        g_e2n_o[i] = __expf(0.5f * f2);
    }
}

// =======================================================================
// fp16 mma.sync attention (m16n8k16), 32-row blocks + 2-way split-J, occ 2.
// grid = (NN/32)*2 = 256; block 512 thr. rowblk = bid>>1, split = bid&1.
// 16 warps = 2 rowgroups x 8 featgroups (CHUNKS = F/64 n8-chunks each).
// p tile fp16 [h][r][j] stride 40 halfs; Wh^T fp16 [feat][j] stride 40 halfs
// (20 words: 20g+c distinct mod 32 -> conflict-free A and B loads).
// Per 32-j tile: sync -> issue wh -> compute p fp16 + STS -> wait+sync ->
// 2 ksteps x CHUNKS mma.m16n8k16. Partials to global; red kernels finish.
// =======================================================================
template <int F, int NH>
__device__ __forceinline__ void attn_body(const __half* __restrict__ WhTh,
                                          const float* __restrict__ e1p,
                                          const float* __restrict__ e1n,
                                          const float* __restrict__ e2p,
                                          const float* __restrict__ e2n,
                                          float* __restrict__ npart,
                                          float* __restrict__ dpart) {
    constexpr int TJ = 32, NT = NN / 2 / TJ;     // 64 tiles per split
    constexpr int PSTR = 40;                     // halfs per p/wh row
    constexpr int CHUNKS = F / 64;               // 4 / 2
    const int tid  = threadIdx.x;
    const int lane = tid & 31, warp = tid >> 5;
    const int g = lane >> 2, c = lane & 3;
    const int rowblk = (int)blockIdx.x >> 1, split = (int)blockIdx.x & 1;
    const int row0 = rowblk * 32;
    const int jbase = split * (NN / 2);
    const int rg = warp >> 3;
    const int feat0 = (warp & 7) * (F / 8);
    const int hw = feat0 / (F / NH);

    __shared__ __align__(16) __half p_s[2][NH * 16 * PSTR];   // [rg][h][r][j]
    __shared__ __align__(16) __half wh_s[F * PSTR];           // [feat][j]

    auto issue_wh = [&](int j0) {
        // F*4 cp16 chunks (16B = 8 j's each); per thread F*4/512
#pragma unroll
        for (int cc = 0; cc < F / 128; cc++) {
            int ch = cc * 512 + tid;
            int feat = ch >> 2, part = ch & 3;
            cp16(sptr(&wh_s[feat * PSTR + part * 8]),
                 &WhTh[feat * NN + j0 + part * 8]);
        }
        cp_commit();
    };

    float d[CHUNKS][4];
#pragma unroll
    for (int q = 0; q < CHUNKS; q++)
#pragma unroll
        for (int i = 0; i < 4; i++) d[q][i] = 0.0f;

    // p-compute role
    int ph, pr, pcq;
    if constexpr (NH == 4) { ph = tid >> 7; pr = (tid >> 3) & 15; pcq = (tid & 7) << 2; }
    else                   { ph = 0;        pr = tid >> 4;        pcq = (tid & 15) << 1; }
    float E1pv0, E1nv0, E1pv1, E1nv1, dsum0 = 0.0f, dsum1 = 0.0f;
    if constexpr (NH == 4) {
        E1pv0 = e1p[ph * NN + row0 + pr];       E1nv0 = e1n[ph * NN + row0 + pr];
        E1pv1 = e1p[ph * NN + row0 + 16 + pr];  E1nv1 = e1n[ph * NN + row0 + 16 + pr];
    } else {
        E1pv0 = e1p[row0 + pr];                 E1nv0 = e1n[row0 + pr];
        E1pv1 = 0.f; E1nv1 = 0.f;
    }

    for (int t = 0; t < NT; t++) {
        const int j0 = jbase + t * TJ;
        __syncthreads();               // mma(t-1) done with p_s and wh_s
        issue_wh(j0);
        // ---- p phase (fp16 round; denominator sums the rounded values) ----
        if constexpr (NH == 4) {
            float4 q2p = *(const float4*)&e2p[ph * NN + j0 + pcq];
            float4 q2n = *(const float4*)&e2n[ph * NN + j0 + pcq];
            float ap[4] = {q2p.x, q2p.y, q2p.z, q2p.w};
            float an[4] = {q2n.x, q2n.y, q2n.z, q2n.w};
            {
                unsigned bw = g_adjbits[(row0 + pr) * (NN / 32) + (j0 >> 5)];
                __half hv[4];
#pragma unroll
                for (int i = 0; i < 4; i++) {
                    float pm = fmaxf(E1pv0 * ap[i], E1nv0 * an[i]);
                    float p  = ((bw >> (pcq + i)) & 1u) ? pm : 0.0f;
                    hv[i] = __float2half_rn(p);
                    dsum0 += __half2float(hv[i]);
                }
                *(uint2*)&p_s[0][(ph * 16 + pr) * PSTR + pcq] = *(uint2*)hv;
            }
            {
                unsigned bw = g_adjbits[(row0 + 16 + pr) * (NN / 32) + (j0 >> 5)];
                __half hv[4];
#pragma unroll
                for (int i = 0; i < 4; i++) {
                    float pm = fmaxf(E1pv1 * ap[i], E1nv1 * an[i]);
                    float p  = ((bw >> (pcq + i)) & 1u) ? pm : 0.0f;
                    hv[i] = __float2half_rn(p);
                    dsum1 += __half2float(hv[i]);
                }
                *(uint2*)&p_s[1][(ph * 16 + pr) * PSTR + pcq] = *(uint2*)hv;
            }
        } else {
            float2 q2p = *(const float2*)&e2p[j0 + pcq];
            float2 q2n = *(const float2*)&e2n[j0 + pcq];
            unsigned bw = g_adjbits[(row0 + pr) * (NN / 32) + (j0 >> 5)];
            float p0 = fmaxf(E1pv0 * q2p.x, E1nv0 * q2n.x);
            float p1 = fmaxf(E1pv0 * q2p.y, E1nv0 * q2n.y);
            p0 = ((bw >> pcq) & 1u) ? p0 : 0.0f;
            p1 = ((bw >> (pcq + 1)) & 1u) ? p1 : 0.0f;
            __half h0 = __float2half_rn(p0), h1 = __float2half_rn(p1);
            dsum0 += __half2float(h0) + __half2float(h1);
            __half hv[2] = {h0, h1};
            *(unsigned*)&p_s[pr >> 4][(pr & 15) * PSTR + pcq] = *(unsigned*)hv;
        }
        cp_wait<0>();
        __syncthreads();               // p_s + wh visible
        // ---- mma: 2 ksteps (k16) x CHUNKS ----
        const unsigned* paw = (const unsigned*)&p_s[rg][hw * 16 * PSTR];
        const unsigned* wsw = (const unsigned*)wh_s;
#pragma unroll
        for (int ks = 0; ks < 2; ks++) {
            unsigned a0 = paw[g * (PSTR / 2) + 8 * ks + c];
            unsigned a1 = paw[(g + 8) * (PSTR / 2) + 8 * ks + c];
            unsigned a2 = paw[g * (PSTR / 2) + 8 * ks + c + 4];
            unsigned a3 = paw[(g + 8) * (PSTR / 2) + 8 * ks + c + 4];
#pragma unroll
            for (int q = 0; q < CHUNKS; q++) {
                int feat = feat0 + q * 8 + g;
                unsigned b0 = wsw[feat * (PSTR / 2) + 8 * ks + c];
                unsigned b1 = wsw[feat * (PSTR / 2) + 8 * ks + c + 4];
                mma_f16(d[q], a0, a1, a2, a3, b0, b1);
            }
        }
    }

    // ---- denominator partials -> global ----
    if constexpr (NH == 4) {
        dsum0 += __shfl_xor_sync(0xffffffffu, dsum0, 1);
        dsum0 += __shfl_xor_sync(0xffffffffu, dsum0, 2);
        dsum0 += __shfl_xor_sync(0xffffffffu, dsum0, 4);
        dsum1 += __shfl_xor_sync(0xffffffffu, dsum1, 1);
        dsum1 += __shfl_xor_sync(0xffffffffu, dsum1, 2);
        dsum1 += __shfl_xor_sync(0xffffffffu, dsum1, 4);
        if ((lane & 7) == 0) {
            dpart[(split * NH1 + ph) * NN + row0 + pr]      = dsum0;
            dpart[(split * NH1 + ph) * NN + row0 + 16 + pr] = dsum1;
        }
    } else {
        dsum0 += __shfl_xor_sync(0xffffffffu, dsum0, 1);
        dsum0 += __shfl_xor_sync(0xffffffffu, dsum0, 2);
        dsum0 += __shfl_xor_sync(0xffffffffu, dsum0, 4);
        dsum0 += __shfl_xor_sync(0xffffffffu, dsum0, 8);
        if ((lane & 15) == 0) dpart[split * NN + row0 + pr] = dsum0;
    }

    // ---- numerator partials -> global ----
    const int orow = row0 + rg * 16;
#pragma unroll
    for (int q = 0; q < CHUNKS; q++) {
        int feat = feat0 + q * 8 + 2 * c;
        *(float2*)&npart[(split * NN + orow + g) * F + feat]     = make_float2(d[q][0], d[q][1]);
        *(float2*)&npart[(split * NN + orow + g + 8) * F + feat] = make_float2(d[q][2], d[q][3]);
    }
}

__global__ void __launch_bounds__(512, 2) attn1_k() {
    attn_body<F1T, NH1>(g_Wh1Th, g_e1p_h, g_e1n_h, g_e2p_h, g_e2n_h, g_np1, g_dp1);
}
__global__ void __launch_bounds__(512, 2) attn2_k() {
    attn_body<F2T, 1>(g_Wh2Th, g_e1p_o, g_e1n_o, g_e2p_o, g_e2n_o, g_np2, g_dp2);
}

// =======================================================================
// split-J reductions: sum 2 partials, divide, ELU
// =======================================================================
__global__ void red1_k() {
    const int i = blockIdx.x, f = threadIdx.x;
    const int h = f >> 6;
    float num = g_np1[i * F1T + f] + g_np1[(NN + i) * F1T + f];
    float den = g_dp1[h * NN + i] + g_dp1[(NH1 + h) * NN + i];
    float v = num / den;
    g_h1[i * F1T + f] = v > 0.0f ? v : expm1f(v);
}
__global__ void red2_k(float* __restrict__ out) {
    const int i = blockIdx.x, f = threadIdx.x;
    float num = g_np2[i * F2T + f] + g_np2[(NN + i) * F2T + f];
    float den = g_dp2[i] + g_dp2[NN + i];
    float v = num / den;
    out[i * F2T + f] = v > 0.0f ? v : expm1f(v);
}

// =======================================================================
extern "C" void kernel_launch(void* const* d_in, const int* in_sizes, int n_in,
                              void* d_out, int out_size) {
    const float* x       = (const float*)d_in[0];
    const int*   adj     = (const int*)  d_in[1];
    const float* W_heads = (const float*)d_in[2];
    const float* a_heads = (const float*)d_in[3];
    const float* W_out   = (const float*)d_in[4];
    const float* a_out   = (const float*)d_in[5];
    float* out = (float*)d_out;

    adjbits_k<<<NN, 128>>>(adj);
    gemm1_k<<<NN / 32, 512>>>(x, W_heads);
    fvec1_k<<<NN, 64>>>(a_heads);
    attn1_k<<<(NN / 32) * 2, 512>>>();
    red1_k<<<NN, F1T>>>();
    gemm2_k<<<NN / 32, 512>>>(W_out);
    fvec2_k<<<NN, 128>>>(a_out);
    attn2_k<<<(NN / 32) * 2, 512>>>();
    red2_k<<<NN, F2T>>>(out);
}